// round 1
// baseline (speedup 1.0000x reference)
#include <cuda_runtime.h>

// HDBLUT 2x superresolution, GB300 sm_103a.
// out[2I+u, 2J+v] = (1/3) * sum over k=0..2, r=0..3 of
//   msb_weight[k][ a*256 + b*16 + c ][ perm_r(u,v) ]
// where a = img[I,J], b = img[refl(I+dbx), refl(J+dby)], c likewise,
// (db,dc) are the rotation-r transformed offsets, refl is mirror reflect
// (t<0 -> -t, t>=2048 -> 4094-t), derived analytically from the
// rot90/pad-reflect reference.
//
// Full 192KB LUT lives in shared memory (1 CTA/SM, persistent grid-stride),
// gathers are LDS.128; 5x5 image patch staged per-warp in smem.

#define NN 2048
#define TILES_PER_ROW 64          // 2048 / 32
#define NTILES (NN * TILES_PER_ROW)
#define WARPS_PER_CTA 16
#define THREADS (WARPS_PER_CTA * 32)
#define PATCH_STRIDE 40           // 36 cols padded
#define LUT_F4 (3 * 4096)
#define SMEM_BYTES (LUT_F4 * 16 + WARPS_PER_CTA * 5 * PATCH_STRIDE * 4)

__device__ __forceinline__ int refl(int t) {
    t = (t < 0) ? -t : t;
    return (t >= NN) ? (2 * NN - 2 - t) : t;
}

__global__ __launch_bounds__(THREADS, 1)
void hdblut_kernel(const int* __restrict__ img,
                   const float4* __restrict__ wlut,
                   float2* __restrict__ out)
{
    extern __shared__ unsigned char smem_raw[];
    float4* slut = reinterpret_cast<float4*>(smem_raw);
    int* spatch = reinterpret_cast<int*>(smem_raw + (size_t)LUT_F4 * sizeof(float4));

    // Cooperative LUT load: 192KB, once per CTA (persistent CTAs -> once per SM)
    for (int i = threadIdx.x; i < LUT_F4; i += THREADS)
        slut[i] = wlut[i];
    __syncthreads();

    const int warp = threadIdx.x >> 5;
    const int lane = threadIdx.x & 31;
    int* patch = spatch + warp * (5 * PATCH_STRIDE);

    const int gwarp = blockIdx.x * WARPS_PER_CTA + warp;
    const int nwarps = gridDim.x * WARPS_PER_CTA;

    for (int t = gwarp; t < NTILES; t += nwarps) {
        const int I  = t >> 6;
        const int Jb = (t & 63) << 5;

        // Stage 5 x 36 patch (rows I-2..I+2, cols Jb-2..Jb+33, reflected)
        #pragma unroll
        for (int i = 0; i < 5; i++) {
            const int ri = refl(I - 2 + i);
            const int* row = img + (size_t)ri * NN;
            patch[i * PATCH_STRIDE + lane] = __ldg(row + refl(Jb - 2 + lane));
            if (lane < 4)
                patch[i * PATCH_STRIDE + 32 + lane] = __ldg(row + refl(Jb + 30 + lane));
        }
        __syncwarp();

        // Per-thread 5x5 neighborhood: v[di][dj] = img[refl(I-2+di), refl(J-2+dj)]
        int v[5][5];
        #pragma unroll
        for (int i = 0; i < 5; i++)
            #pragma unroll
            for (int j = 0; j < 5; j++)
                v[i][j] = patch[i * PATCH_STRIDE + lane + j];
        __syncwarp();   // reads done before next iteration overwrites

        const int a256 = v[2][2] << 8;
        float o00 = 0.f, o01 = 0.f, o10 = 0.f, o11 = 0.f;

        // perm per rotation r (w-element feeding out00,out01,out10,out11):
        //   r=0: (x,y,z,w)   r=1: (z,x,w,y)   r=2: (w,z,y,x)   r=3: (y,w,x,z)
        #define TERM(k, bx, by, cx, cy, P00, P01, P10, P11) do {                 \
            int idx_ = a256 + (v[2+(bx)][2+(by)] << 4) + v[2+(cx)][2+(cy)];      \
            float4 w_ = slut[(k) * 4096 + idx_];                                 \
            o00 += w_.P00; o01 += w_.P01; o10 += w_.P10; o11 += w_.P11;          \
        } while (0)

        // r = 0: offsets (x,y) as-is
        TERM(0,  0, 1,  0, 2,  x, y, z, w);
        TERM(1,  1, 1,  2, 2,  x, y, z, w);
        TERM(2,  1, 2,  2, 1,  x, y, z, w);
        // r = 1: (x,y) -> (y,-x)
        TERM(0,  1, 0,  2, 0,  z, x, w, y);
        TERM(1,  1,-1,  2,-2,  z, x, w, y);
        TERM(2,  2,-1,  1,-2,  z, x, w, y);
        // r = 2: (x,y) -> (-x,-y)
        TERM(0,  0,-1,  0,-2,  w, z, y, x);
        TERM(1, -1,-1, -2,-2,  w, z, y, x);
        TERM(2, -1,-2, -2,-1,  w, z, y, x);
        // r = 3: (x,y) -> (-y,x)
        TERM(0, -1, 0, -2, 0,  y, w, x, z);
        TERM(1, -1, 1, -2, 2,  y, w, x, z);
        TERM(2, -2, 1, -1, 2,  y, w, x, z);

        #undef TERM

        const float s = 1.0f / 3.0f;
        const int J = Jb + lane;
        // out rows 2I and 2I+1, cols 2J..2J+1; row = 4096 floats = 2048 float2
        out[(size_t)(2 * I)     * 2048 + J] = make_float2(o00 * s, o01 * s);
        out[(size_t)(2 * I + 1) * 2048 + J] = make_float2(o10 * s, o11 * s);
    }
}

extern "C" void kernel_launch(void* const* d_in, const int* in_sizes, int n_in,
                              void* d_out, int out_size)
{
    const int*    img  = (const int*)d_in[0];
    const float4* wlut = (const float4*)d_in[1];
    float2*       out  = (float2*)d_out;

    int sms = 0;
    cudaDeviceGetAttribute(&sms, cudaDevAttrMultiProcessorCount, 0);
    if (sms <= 0) sms = 148;

    cudaFuncSetAttribute(hdblut_kernel,
                         cudaFuncAttributeMaxDynamicSharedMemorySize, SMEM_BYTES);

    hdblut_kernel<<<sms, THREADS, SMEM_BYTES>>>(img, wlut, out);
}

// round 2
// speedup vs baseline: 1.6268x; 1.6268x over previous
#include <cuda_runtime.h>
#include <cuda_fp16.h>

// HDBLUT 2x superresolution, GB300 sm_103a. Round 2:
//  - LUT converted to fp16 (half4, 1/3 scale folded in) -> LDS.64 gathers
//  - image nibble-packed (8 px / word) with reflect padding baked in
//  - full 96KB fp16 LUT in shared memory, 1 persistent CTA/SM, 24 warps

#define NN 2048
#define NTILES (NN * 64)          // 32-pixel warp tiles
#define WARPS_PER_CTA 24
#define THREADS (WARPS_PER_CTA * 32)
#define LUT_E (3 * 4096)
#define PSTRIDE 260               // words per packed row (257 used)
#define PWORDS 257
#define SMEM_BYTES (LUT_E * 8)

__device__ uint2    g_lut[LUT_E];            // half4 per entry, 96 KB
__device__ unsigned g_pimg[NN * PSTRIDE];    // nibble-packed, ~2.1 MB

__device__ __forceinline__ int refl(int t) {
    t = (t < 0) ? -t : t;
    return (t >= NN) ? (2 * NN - 2 - t) : t;
}

// One prelude kernel: converts LUT to scaled fp16 and nibble-packs the image.
__global__ void hdblut_prelude(const int* __restrict__ img,
                               const float4* __restrict__ w)
{
    int gid = blockIdx.x * blockDim.x + threadIdx.x;
    if (gid < LUT_E) {
        float4 v = w[gid];
        const float s = 1.0f / 3.0f;
        __half2 lo = __floats2half2_rn(v.x * s, v.y * s);
        __half2 hi = __floats2half2_rn(v.z * s, v.w * s);
        uint2 u;
        u.x = *reinterpret_cast<unsigned*>(&lo);
        u.y = *reinterpret_cast<unsigned*>(&hi);
        g_lut[gid] = u;
    }
    int pid = gid - LUT_E;
    if (pid >= 0 && pid < NN * PWORDS) {
        int r  = pid / PWORDS;
        int wi = pid - r * PWORDS;
        const int* row = img + (size_t)r * NN;
        unsigned val = 0;
        #pragma unroll
        for (int j = 0; j < 8; j++) {
            int col = wi * 8 + j - 2;            // packed col -> image col
            col = (col < 0) ? -col : col;
            col = (col >= NN) ? (2 * NN - 2 - col) : col;
            val |= (unsigned)(row[col] & 15) << (4 * j);
        }
        g_pimg[(size_t)r * PSTRIDE + wi] = val;
    }
}

__global__ __launch_bounds__(THREADS, 1)
void hdblut_main(float2* __restrict__ out)
{
    extern __shared__ uint2 slut[];   // 96 KB fp16 LUT

    for (int i = threadIdx.x; i < LUT_E; i += THREADS)
        slut[i] = g_lut[i];
    __syncthreads();

    const int warp = threadIdx.x >> 5;
    const int lane = threadIdx.x & 31;
    const int gwarp  = blockIdx.x * WARPS_PER_CTA + warp;
    const int nwarps = gridDim.x * WARPS_PER_CTA;

    for (int t = gwarp; t < NTILES; t += nwarps) {
        const int I  = t >> 6;
        const int Jb = (t & 63) << 5;

        // 5 packed rows: r_[i] holds nibbles for cols J-2..J+2 (J = Jb+lane)
        unsigned r_[5];
        const int pos = Jb + lane;          // packed-nibble position of col J-2
        const int wi  = pos >> 3;
        const int sh  = (pos & 7) * 4;
        #pragma unroll
        for (int i = 0; i < 5; i++) {
            const unsigned* pr = g_pimg + (size_t)refl(I - 2 + i) * PSTRIDE;
            unsigned w0 = __ldg(pr + wi);
            unsigned w1 = __ldg(pr + wi + 1);
            r_[i] = __funnelshift_r(w0, w1, sh);
        }

        const int a8 = (int)((r_[2] >> 8) & 15u) << 8;

        float o00 = 0.f, o01 = 0.f, o10 = 0.f, o11 = 0.f;

        // perm per rotation r (half4 element feeding o00,o01,o10,o11):
        //   r=0: (0,1,2,3)  r=1: (2,0,3,1)  r=2: (3,2,1,0)  r=3: (1,3,0,2)
        #define TERM(k, bx, by, cx, cy, i00, i01, i10, i11) do {                  \
            int b_ = (int)((r_[2+(bx)] >> (4*(2+(by)))) & 15u);                    \
            int c_ = (int)((r_[2+(cx)] >> (4*(2+(cy)))) & 15u);                    \
            uint2 h_ = slut[(k)*4096 + a8 + (b_ << 4) + c_];                       \
            float2 f0 = __half22float2(*reinterpret_cast<__half2*>(&h_.x));       \
            float2 f1 = __half22float2(*reinterpret_cast<__half2*>(&h_.y));       \
            float fv_[4] = {f0.x, f0.y, f1.x, f1.y};                               \
            o00 += fv_[i00]; o01 += fv_[i01]; o10 += fv_[i10]; o11 += fv_[i11];    \
        } while (0)

        // r = 0: offsets as-is
        TERM(0,  0, 1,  0, 2,  0,1,2,3);
        TERM(1,  1, 1,  2, 2,  0,1,2,3);
        TERM(2,  1, 2,  2, 1,  0,1,2,3);
        // r = 1: (x,y) -> (y,-x)
        TERM(0,  1, 0,  2, 0,  2,0,3,1);
        TERM(1,  1,-1,  2,-2,  2,0,3,1);
        TERM(2,  2,-1,  1,-2,  2,0,3,1);
        // r = 2: (x,y) -> (-x,-y)
        TERM(0,  0,-1,  0,-2,  3,2,1,0);
        TERM(1, -1,-1, -2,-2,  3,2,1,0);
        TERM(2, -1,-2, -2,-1,  3,2,1,0);
        // r = 3: (x,y) -> (-y,x)
        TERM(0, -1, 0, -2, 0,  1,3,0,2);
        TERM(1, -1, 1, -2, 2,  1,3,0,2);
        TERM(2, -2, 1, -1, 2,  1,3,0,2);

        #undef TERM

        const int J = Jb + lane;
        out[(size_t)(2 * I)     * 2048 + J] = make_float2(o00, o01);
        out[(size_t)(2 * I + 1) * 2048 + J] = make_float2(o10, o11);
    }
}

extern "C" void kernel_launch(void* const* d_in, const int* in_sizes, int n_in,
                              void* d_out, int out_size)
{
    const int*    img  = (const int*)d_in[0];
    const float4* wlut = (const float4*)d_in[1];
    float2*       out  = (float2*)d_out;

    int sms = 0;
    cudaDeviceGetAttribute(&sms, cudaDevAttrMultiProcessorCount, 0);
    if (sms <= 0) sms = 148;

    // prelude: LUT_E + NN*PWORDS work items
    int total = LUT_E + NN * PWORDS;
    hdblut_prelude<<<(total + 255) / 256, 256>>>(img, wlut);

    cudaFuncSetAttribute(hdblut_main,
                         cudaFuncAttributeMaxDynamicSharedMemorySize, SMEM_BYTES);
    hdblut_main<<<sms, THREADS, SMEM_BYTES>>>(out);
}

// round 3
// speedup vs baseline: 1.6993x; 1.0446x over previous
#include <cuda_runtime.h>
#include <cuda_fp16.h>

// HDBLUT 2x superresolution, GB300 sm_103a. Round 3:
//  - 2 CTAs/SM x 512 threads (32 warps/SM), each CTA holds full 96KB fp16 LUT
//  - per-rotation half2 tree accumulation (4 HADD2 + 4 CVT + 4 FADD)
//  - 2 pixel rows per warp iteration (6 shared packed patch rows)

#define NN 2048
#define NTILES (1024 * 64)        // row-pairs x 32-col tiles
#define THREADS 512
#define WARPS_PER_CTA (THREADS / 32)
#define LUT_E (3 * 4096)
#define PSTRIDE 260
#define PWORDS 257
#define SMEM_BYTES (LUT_E * 8)

__device__ uint2    g_lut[LUT_E];            // half4 per entry, 96 KB
__device__ unsigned g_pimg[NN * PSTRIDE];    // nibble-packed image

__device__ __forceinline__ int refl(int t) {
    t = (t < 0) ? -t : t;
    return (t >= NN) ? (2 * NN - 2 - t) : t;
}

__device__ __forceinline__ __half2 u2h(unsigned u) {
    return *reinterpret_cast<__half2*>(&u);
}

__global__ void hdblut_prelude(const int* __restrict__ img,
                               const float4* __restrict__ w)
{
    int gid = blockIdx.x * blockDim.x + threadIdx.x;
    if (gid < LUT_E) {
        float4 v = w[gid];
        const float s = 1.0f / 3.0f;
        __half2 lo = __floats2half2_rn(v.x * s, v.y * s);
        __half2 hi = __floats2half2_rn(v.z * s, v.w * s);
        uint2 u;
        u.x = *reinterpret_cast<unsigned*>(&lo);
        u.y = *reinterpret_cast<unsigned*>(&hi);
        g_lut[gid] = u;
    }
    int pid = gid - LUT_E;
    if (pid >= 0 && pid < NN * PWORDS) {
        int r  = pid / PWORDS;
        int wi = pid - r * PWORDS;
        const int* row = img + (size_t)r * NN;
        unsigned val = 0;
        #pragma unroll
        for (int j = 0; j < 8; j++) {
            int col = wi * 8 + j - 2;
            col = (col < 0) ? -col : col;
            col = (col >= NN) ? (2 * NN - 2 - col) : col;
            val |= (unsigned)(row[col] & 15) << (4 * j);
        }
        g_pimg[(size_t)r * PSTRIDE + wi] = val;
    }
}

__global__ __launch_bounds__(THREADS, 2)
void hdblut_main(float2* __restrict__ out)
{
    extern __shared__ uint2 slut[];   // 96 KB fp16 LUT

    for (int i = threadIdx.x; i < LUT_E; i += THREADS)
        slut[i] = g_lut[i];
    __syncthreads();

    const int warp = threadIdx.x >> 5;
    const int lane = threadIdx.x & 31;
    const int gwarp  = blockIdx.x * WARPS_PER_CTA + warp;
    const int nwarps = gridDim.x * WARPS_PER_CTA;

    for (int t = gwarp; t < NTILES; t += nwarps) {
        const int I  = (t >> 6) << 1;       // even low-res row, pair (I, I+1)
        const int Jb = (t & 63) << 5;

        // 6 packed rows I-2..I+3; r_[i] holds nibbles for cols J-2.. (J=Jb+lane)
        unsigned r_[6];
        const int pos = Jb + lane;
        const int wi  = pos >> 3;
        const int sh  = (pos & 7) * 4;
        #pragma unroll
        for (int i = 0; i < 6; i++) {
            const unsigned* pr = g_pimg + (size_t)refl(I - 2 + i) * PSTRIDE;
            unsigned w0 = __ldg(pr + wi);
            unsigned w1 = __ldg(pr + wi + 1);
            r_[i] = __funnelshift_r(w0, w1, sh);
        }

        float acc[2][4];
        #pragma unroll
        for (int ro = 0; ro < 2; ro++)
            acc[ro][0] = acc[ro][1] = acc[ro][2] = acc[ro][3] = 0.f;

        #define NIB(i, j)  ((int)((r_[(i)] >> (4 * (j))) & 15u))
        #define GIDX(ro, k, bx, by, cx, cy) \
            ((k) * 4096 + a8 + (NIB(2 + (ro) + (bx), 2 + (by)) << 4) \
                            +  NIB(2 + (ro) + (cx), 2 + (cy)))

        // One rotation = 3 gathers (k=0,1,2) sharing a permutation:
        //   r=0: (0,1,2,3)  r=1: (2,0,3,1)  r=2: (3,2,1,0)  r=3: (1,3,0,2)
        #define ROT3(ro, b0x,b0y,c0x,c0y, b1x,b1y,c1x,c1y, b2x,b2y,c2x,c2y, \
                     i00,i01,i10,i11) do {                                  \
            uint2 h0 = slut[GIDX(ro, 0, b0x,b0y, c0x,c0y)];                 \
            uint2 h1 = slut[GIDX(ro, 1, b1x,b1y, c1x,c1y)];                 \
            uint2 h2 = slut[GIDX(ro, 2, b2x,b2y, c2x,c2y)];                 \
            __half2 sA = __hadd2(__hadd2(u2h(h0.x), u2h(h1.x)), u2h(h2.x)); \
            __half2 sB = __hadd2(__hadd2(u2h(h0.y), u2h(h1.y)), u2h(h2.y)); \
            float2 fA = __half22float2(sA);                                 \
            float2 fB = __half22float2(sB);                                 \
            float fv[4] = {fA.x, fA.y, fB.x, fB.y};                         \
            acc[ro][0] += fv[i00]; acc[ro][1] += fv[i01];                   \
            acc[ro][2] += fv[i10]; acc[ro][3] += fv[i11];                   \
        } while (0)

        #pragma unroll
        for (int ro = 0; ro < 2; ro++) {
            const int a8 = NIB(2 + ro, 2) << 8;
            // r = 0: offsets as-is
            ROT3(ro,  0, 1,  0, 2,   1, 1,  2, 2,   1, 2,  2, 1,  0,1,2,3);
            // r = 1: (x,y) -> (y,-x)
            ROT3(ro,  1, 0,  2, 0,   1,-1,  2,-2,   2,-1,  1,-2,  2,0,3,1);
            // r = 2: (x,y) -> (-x,-y)
            ROT3(ro,  0,-1,  0,-2,  -1,-1, -2,-2,  -1,-2, -2,-1,  3,2,1,0);
            // r = 3: (x,y) -> (-y,x)
            ROT3(ro, -1, 0, -2, 0,  -1, 1, -2, 2,  -2, 1, -1, 2,  1,3,0,2);
        }

        #undef ROT3
        #undef GIDX
        #undef NIB

        const int J = Jb + lane;
        const size_t base = (size_t)(2 * I) * 2048 + J;   // out row 2I, float2 cols
        out[base         ] = make_float2(acc[0][0], acc[0][1]);
        out[base + 2048  ] = make_float2(acc[0][2], acc[0][3]);
        out[base + 4096  ] = make_float2(acc[1][0], acc[1][1]);
        out[base + 6144  ] = make_float2(acc[1][2], acc[1][3]);
    }
}

extern "C" void kernel_launch(void* const* d_in, const int* in_sizes, int n_in,
                              void* d_out, int out_size)
{
    const int*    img  = (const int*)d_in[0];
    const float4* wlut = (const float4*)d_in[1];
    float2*       out  = (float2*)d_out;

    int sms = 0;
    cudaDeviceGetAttribute(&sms, cudaDevAttrMultiProcessorCount, 0);
    if (sms <= 0) sms = 148;

    int total = LUT_E + NN * PWORDS;
    hdblut_prelude<<<(total + 255) / 256, 256>>>(img, wlut);

    cudaFuncSetAttribute(hdblut_main,
                         cudaFuncAttributeMaxDynamicSharedMemorySize, SMEM_BYTES);
    hdblut_main<<<2 * sms, THREADS, SMEM_BYTES>>>(out);
}